// round 2
// baseline (speedup 1.0000x reference)
#include <cuda_runtime.h>
#include <cuda_bf16.h>
#include <cstdint>
#include <cstddef>

#define NCTA   148
#define TSTEPS 2048

// SMEM layout (dynamic): sv activations 16KB | P1 cached pair 12KB | P2 cached pairs 192KB
#define SV_BYTES    16384
#define CP1_BYTES   12288                    // 2 rows x 3072 bf16
#define NCACHE_P2   12
#define CP2_BYTES   (NCACHE_P2 * 2 * 4096 * 2)   // 196608
#define SMEM_TOTAL  (SV_BYTES + CP1_BYTES + CP2_BYTES)   // 225280

// ---------------- static device storage (allowed scratch) ----------------
__device__ __align__(16) __nv_bfloat16 g_W1t[(size_t)512  * 2560]; // [out][in] in=[h2(2048);x(512)]
__device__ __align__(16) __nv_bfloat16 g_J1t[(size_t)2048 * 3072];
__device__ __align__(16) __nv_bfloat16 g_K1t[(size_t)2048 * 3072];
__device__ __align__(16) __nv_bfloat16 g_J2t[(size_t)2048 * 4096];
__device__ __align__(16) __nv_bfloat16 g_K2t[(size_t)2048 * 4096];
__device__ __align__(16) __nv_bfloat16 g_W2t[(size_t)512  * 2048];

__device__ float g_a[512];
__device__ float g_out[512];
__device__ float g_h1[2][2048];
__device__ float g_h2[2][2048];
__device__ unsigned g_bar;

// ---------------- transpose + fp32->bf16 convert ----------------
__global__ void transpose_convert(const float* __restrict__ src, int which, int fi, int fo)
{
    __shared__ float tile[32][33];
    __nv_bfloat16* dst =
        which == 0 ? g_W1t : which == 1 ? g_J1t : which == 2 ? g_K1t :
        which == 3 ? g_J2t : which == 4 ? g_K2t : g_W2t;
    int o0 = blockIdx.x * 32, i0 = blockIdx.y * 32;
    for (int r = threadIdx.y; r < 32; r += 8)
        tile[r][threadIdx.x] = src[(size_t)(i0 + r) * fo + o0 + threadIdx.x];
    __syncthreads();
    for (int r = threadIdx.y; r < 32; r += 8)
        dst[(size_t)(o0 + r) * fi + i0 + threadIdx.x] = __float2bfloat16(tile[threadIdx.x][r]);
}

__global__ void init_state()
{
    int i = blockIdx.x * blockDim.x + threadIdx.x;
    if (i == 0) g_bar = 0u;
    if (i < 512) g_out[i] = 0.f;
    if (i < 2048) { g_h1[0][i] = 0.f; g_h2[0][i] = 0.f; }
}

// ---------------- helpers ----------------
__device__ __forceinline__ float bflo(unsigned w) { return __uint_as_float(w << 16); }
__device__ __forceinline__ float bfhi(unsigned w) { return __uint_as_float(w & 0xffff0000u); }

// 16B-granular XOR swizzle for the activation vector
__device__ __forceinline__ int swz(int i) { return i ^ (((i >> 5) & 1) << 2); }

__device__ __forceinline__ float wredsum(float a)
{
#pragma unroll
    for (int o = 16; o > 0; o >>= 1) a += __shfl_xor_sync(0xffffffffu, a, o);
    return a;
}

// dual-row dot: J-row and K-row share the activation reads.
// Works for weights in GMEM or SMEM (inlined; address space resolved per call site).
template <int NIT>
__device__ __forceinline__ float2 dotrow2(const __nv_bfloat16* __restrict__ wj,
                                          const __nv_bfloat16* __restrict__ wk,
                                          const float* __restrict__ v, int lane)
{
    const uint4* wpj = (const uint4*)wj;
    const uint4* wpk = (const uint4*)wk;
    float aj0 = 0.f, aj1 = 0.f, ak0 = 0.f, ak1 = 0.f;
#pragma unroll 4
    for (int it = 0; it < NIT; it++) {
        int base = it * 256 + lane * 8;
        float4 a = *(const float4*)(v + swz(base));
        float4 b = *(const float4*)(v + swz(base + 4));
        uint4 uj = wpj[it * 32 + lane];
        uint4 uk = wpk[it * 32 + lane];
        aj0 = fmaf(bflo(uj.x), a.x, aj0); aj1 = fmaf(bfhi(uj.x), a.y, aj1);
        aj0 = fmaf(bflo(uj.y), a.z, aj0); aj1 = fmaf(bfhi(uj.y), a.w, aj1);
        aj0 = fmaf(bflo(uj.z), b.x, aj0); aj1 = fmaf(bfhi(uj.z), b.y, aj1);
        aj0 = fmaf(bflo(uj.w), b.z, aj0); aj1 = fmaf(bfhi(uj.w), b.w, aj1);
        ak0 = fmaf(bflo(uk.x), a.x, ak0); ak1 = fmaf(bfhi(uk.x), a.y, ak1);
        ak0 = fmaf(bflo(uk.y), a.z, ak0); ak1 = fmaf(bfhi(uk.y), a.w, ak1);
        ak0 = fmaf(bflo(uk.z), b.x, ak0); ak1 = fmaf(bfhi(uk.z), b.y, ak1);
        ak0 = fmaf(bflo(uk.w), b.z, ak0); ak1 = fmaf(bfhi(uk.w), b.w, ak1);
    }
    return make_float2(aj0 + aj1, ak0 + ak1);
}

template <int NIT>
__device__ __forceinline__ float dotrow(const __nv_bfloat16* __restrict__ w,
                                        const float* __restrict__ v, int lane)
{
    const uint4* wp = (const uint4*)w;
    float a0 = 0.f, a1 = 0.f;
#pragma unroll 4
    for (int it = 0; it < NIT; it++) {
        int base = it * 256 + lane * 8;
        float4 a = *(const float4*)(v + swz(base));
        float4 b = *(const float4*)(v + swz(base + 4));
        uint4 u = wp[it * 32 + lane];
        a0 = fmaf(bflo(u.x), a.x, a0); a1 = fmaf(bfhi(u.x), a.y, a1);
        a0 = fmaf(bflo(u.y), a.z, a0); a1 = fmaf(bfhi(u.y), a.w, a1);
        a0 = fmaf(bflo(u.z), b.x, a0); a1 = fmaf(bfhi(u.z), b.y, a1);
        a0 = fmaf(bflo(u.w), b.z, a0); a1 = fmaf(bfhi(u.w), b.w, a1);
    }
    return a0 + a1;
}

__device__ __forceinline__ float sigm(float z) { return 1.f / (1.f + __expf(-z)); }

// monotonic-counter grid barrier (all CTAs resident: grid=148)
__device__ __forceinline__ void gsync(unsigned& target)
{
    __syncthreads();
    if (threadIdx.x == 0) {
        __threadfence();
        atomicAdd(&g_bar, 1u);
        target += NCTA;
        unsigned v;
        do {
            asm volatile("ld.acquire.gpu.u32 %0, [%1];" : "=r"(v) : "l"(&g_bar) : "memory");
        } while (v < target);
    }
    __syncthreads();
}

// ---------------- persistent RNN kernel ----------------
__global__ __launch_bounds__(1024, 1) void rnn_kernel(
    const float* __restrict__ X,
    const float* __restrict__ b1,  const float* __restrict__ J1b, const float* __restrict__ K1b,
    const float* __restrict__ J2b, const float* __restrict__ K2b, const float* __restrict__ b2,
    float* __restrict__ Y)
{
    extern __shared__ __align__(16) unsigned char smem_raw[];
    float* sv = (float*)smem_raw;                                        // 4096 floats
    __nv_bfloat16* cP1 = (__nv_bfloat16*)(smem_raw + SV_BYTES);          // [2][3072]
    __nv_bfloat16* cP2 = (__nv_bfloat16*)(smem_raw + SV_BYTES + CP1_BYTES); // [12][2][4096]

    const int tid  = threadIdx.x;
    const int lane = tid & 31;
    const int wid  = tid >> 5;
    const int cta  = blockIdx.x;
    const int r    = wid * NCTA + cta;   // global work index for this warp
    unsigned target = 0;

    // ---- fill SMEM weight cache (once) ----
    {
        // phase-1 pair for row = cta (the wid==0 row of this CTA)
        const uint4* srcJ = (const uint4*)&g_J1t[(size_t)cta * 3072];
        const uint4* srcK = (const uint4*)&g_K1t[(size_t)cta * 3072];
        uint4* dJ = (uint4*)cP1;
        uint4* dK = (uint4*)(cP1 + 3072);
        for (int i = tid; i < 384; i += 1024) { dJ[i] = srcJ[i]; dK[i] = srcK[i]; }
        // phase-2 pairs for rows q*148+cta, q = 0..11
        for (int q = 0; q < NCACHE_P2; q++) {
            const size_t row = (size_t)(q * NCTA + cta) * 4096;
            const uint4* sJ = (const uint4*)&g_J2t[row];
            const uint4* sK = (const uint4*)&g_K2t[row];
            uint4* dJ2 = (uint4*)(cP2 + (size_t)q * 8192);
            uint4* dK2 = (uint4*)(cP2 + (size_t)q * 8192 + 4096);
            for (int i = tid; i < 512; i += 1024) { dJ2[i] = sJ[i]; dK2[i] = sK[i]; }
        }
    }

    // ---- pre-phase: a_0 = b1 + W1[x-part]^T x_0   (h2 = 0)
    for (int i = tid; i < 512; i += 1024) sv[swz(i)] = X[i];
    __syncthreads();
    if (r < 512) {
        float acc = dotrow<2>(&g_W1t[(size_t)r * 2560 + 2048], sv, lane);
        acc = wredsum(acc);
        if (lane == 0) g_a[r] = acc + b1[r];
    }
    gsync(target);

    for (int t = 0; t < TSTEPS; t++) {
        const int p = t & 1;

        // ---- phase 1: c1=[a; out; h1_old], compute h1_new
        for (int i = tid; i < 512; i += 1024) {
            sv[swz(i)]       = __ldcg(&g_a[i]);
            sv[swz(512 + i)] = __ldcg(&g_out[i]);
        }
        for (int i = tid; i < 2048; i += 1024) sv[swz(1024 + i)] = __ldcg(&g_h1[p][i]);
        __syncthreads();
        if (r < 2048) {
            float2 zz;
            if (wid == 0)
                zz = dotrow2<12>(cP1, cP1 + 3072, sv, lane);                     // SMEM weights
            else
                zz = dotrow2<12>(&g_J1t[(size_t)r * 3072], &g_K1t[(size_t)r * 3072], sv, lane);
            float zj = wredsum(zz.x);
            float zk = wredsum(zz.y);
            if (lane == 0) {
                float j = sigm(zj + J1b[r]);
                float k = sigm(zk + K1b[r]);
                float h = __ldcg(&g_h1[p][r]);
                g_h1[p ^ 1][r] = fmaf(j, 1.f - h, (1.f - k) * h);
            }
        }
        gsync(target);

        // ---- phase 2: c2=[h1_new; h2_old], compute h2_new
        for (int i = tid; i < 2048; i += 1024) {
            sv[swz(i)]        = __ldcg(&g_h1[p ^ 1][i]);
            sv[swz(2048 + i)] = __ldcg(&g_h2[p][i]);
        }
        __syncthreads();
        if (r < 2048) {
            float2 zz;
            if (wid < NCACHE_P2) {
                const __nv_bfloat16* base = cP2 + (size_t)wid * 8192;
                zz = dotrow2<16>(base, base + 4096, sv, lane);                   // SMEM weights
            } else {
                zz = dotrow2<16>(&g_J2t[(size_t)r * 4096], &g_K2t[(size_t)r * 4096], sv, lane);
            }
            float zj = wredsum(zz.x);
            float zk = wredsum(zz.y);
            if (lane == 0) {
                float j = sigm(zj + J2b[r]);
                float k = sigm(zk + K2b[r]);
                float h = __ldcg(&g_h2[p][r]);
                g_h2[p ^ 1][r] = fmaf(j, 1.f - h, (1.f - k) * h);
            }
        }
        gsync(target);

        // ---- phase 3: out_t = sigmoid(W2^T h2_new + b2); a_{t+1} = W1^T [h2_new; x_{t+1}] + b1
        const bool hasNext = (t + 1) < TSTEPS;
        for (int i = tid; i < 2048; i += 1024) sv[swz(i)] = __ldcg(&g_h2[p ^ 1][i]);
        if (hasNext)
            for (int i = tid; i < 512; i += 1024) sv[swz(2048 + i)] = X[(size_t)(t + 1) * 512 + i];
        __syncthreads();
        if (r < 512) {
            float acc = dotrow<8>(&g_W2t[(size_t)r * 2048], sv, lane);
            acc = wredsum(acc);
            if (lane == 0) {
                float s = sigm(acc + b2[r]);
                g_out[r] = s;
                Y[(size_t)t * 512 + r] = s;
            }
        } else if (r < 1024 && hasNext) {
            const int i = r - 512;
            float acc = dotrow<10>(&g_W1t[(size_t)i * 2560], sv, lane);
            acc = wredsum(acc);
            if (lane == 0) g_a[i] = acc + b1[i];
        }
        gsync(target);
    }
}

// ---------------- launch ----------------
extern "C" void kernel_launch(void* const* d_in, const int* in_sizes, int n_in,
                              void* d_out, int out_size)
{
    (void)in_sizes; (void)n_in; (void)out_size;
    const float* X   = (const float*)d_in[0];
    const float* W1  = (const float*)d_in[1];
    const float* b1  = (const float*)d_in[2];
    const float* J1W = (const float*)d_in[3];
    const float* J1b = (const float*)d_in[4];
    const float* K1W = (const float*)d_in[5];
    const float* K1b = (const float*)d_in[6];
    const float* J2W = (const float*)d_in[7];
    const float* J2b = (const float*)d_in[8];
    const float* K2W = (const float*)d_in[9];
    const float* K2b = (const float*)d_in[10];
    const float* W2  = (const float*)d_in[11];
    const float* b2  = (const float*)d_in[12];
    float* Y = (float*)d_out;

    cudaFuncSetAttribute(rnn_kernel, cudaFuncAttributeMaxDynamicSharedMemorySize, SMEM_TOTAL);

    dim3 tb(32, 8);
    transpose_convert<<<dim3(512 / 32, 2560 / 32), tb>>>(W1, 0, 2560, 512);
    transpose_convert<<<dim3(2048 / 32, 3072 / 32), tb>>>(J1W, 1, 3072, 2048);
    transpose_convert<<<dim3(2048 / 32, 3072 / 32), tb>>>(K1W, 2, 3072, 2048);
    transpose_convert<<<dim3(2048 / 32, 4096 / 32), tb>>>(J2W, 3, 4096, 2048);
    transpose_convert<<<dim3(2048 / 32, 4096 / 32), tb>>>(K2W, 4, 4096, 2048);
    transpose_convert<<<dim3(512 / 32, 2048 / 32), tb>>>(W2, 5, 2048, 512);
    init_state<<<2, 1024>>>();
    rnn_kernel<<<NCTA, 1024, SMEM_TOTAL>>>(X, b1, J1b, K1b, J2b, K2b, b2, Y);
}

// round 6
// speedup vs baseline: 1.6790x; 1.6790x over previous
#include <cuda_runtime.h>
#include <cuda_bf16.h>
#include <cstdint>
#include <cstddef>

#define NCTA   148
#define TSTEPS 2048

// ---------------- static device storage (allowed scratch) ----------------
__device__ __align__(16) __nv_bfloat16 g_W1t[(size_t)512  * 2560]; // [out][in] in=[h2(2048);x(512)]
__device__ __align__(16) __nv_bfloat16 g_J1t[(size_t)2048 * 3072];
__device__ __align__(16) __nv_bfloat16 g_K1t[(size_t)2048 * 3072];
__device__ __align__(16) __nv_bfloat16 g_J2t[(size_t)2048 * 4096];
__device__ __align__(16) __nv_bfloat16 g_K2t[(size_t)2048 * 4096];
__device__ __align__(16) __nv_bfloat16 g_W2t[(size_t)512  * 2048];

__device__ float g_a[512];
__device__ float g_out[512];
__device__ float g_h1[2][2048];
__device__ float g_h2[2][2048];
__device__ unsigned g_bar;

// ---------------- transpose + fp32->bf16 convert ----------------
__global__ void transpose_convert(const float* __restrict__ src, int which, int fi, int fo)
{
    __shared__ float tile[32][33];
    __nv_bfloat16* dst =
        which == 0 ? g_W1t : which == 1 ? g_J1t : which == 2 ? g_K1t :
        which == 3 ? g_J2t : which == 4 ? g_K2t : g_W2t;
    int o0 = blockIdx.x * 32, i0 = blockIdx.y * 32;
    for (int r = threadIdx.y; r < 32; r += 8)
        tile[r][threadIdx.x] = src[(size_t)(i0 + r) * fo + o0 + threadIdx.x];
    __syncthreads();
    for (int r = threadIdx.y; r < 32; r += 8)
        dst[(size_t)(o0 + r) * fi + i0 + threadIdx.x] = __float2bfloat16(tile[threadIdx.x][r]);
}

__global__ void init_state()
{
    int i = blockIdx.x * blockDim.x + threadIdx.x;
    if (i == 0) g_bar = 0u;
    if (i < 512) g_out[i] = 0.f;
    if (i < 2048) { g_h1[0][i] = 0.f; g_h2[0][i] = 0.f; }
}

// ---------------- helpers ----------------
__device__ __forceinline__ float bflo(unsigned w) { return __uint_as_float(w << 16); }
__device__ __forceinline__ float bfhi(unsigned w) { return __uint_as_float(w & 0xffff0000u); }

// 16B-granular XOR swizzle (conflict-free LDS.128 for lane*32B pattern).
// Uniform within an aligned float4, so float4 ld/st through swz is legal.
__device__ __forceinline__ int swz(int i) { return i ^ (((i >> 5) & 1) << 2); }

__device__ __forceinline__ float wredsum(float a)
{
#pragma unroll
    for (int o = 16; o > 0; o >>= 1) a += __shfl_xor_sync(0xffffffffu, a, o);
    return a;
}

__device__ __forceinline__ uint4 ldcg16(const __nv_bfloat16* p)
{
    return __ldcg((const uint4*)p);
}

// dual-row dot: J-row and K-row share the activation reads (weights streamed L2-only).
// Each iteration consumes 256 activations (8 per lane) and 256 bf16 weights per row.
template <int NIT>
__device__ __forceinline__ float2 dotrow2(const __nv_bfloat16* __restrict__ wj,
                                          const __nv_bfloat16* __restrict__ wk,
                                          const float* __restrict__ v, int lane)
{
    float aj0 = 0.f, aj1 = 0.f, ak0 = 0.f, ak1 = 0.f;
#pragma unroll 4
    for (int it = 0; it < NIT; it++) {
        int base = it * 256 + lane * 8;
        float4 a = *(const float4*)(v + swz(base));
        float4 b = *(const float4*)(v + swz(base + 4));
        uint4 uj = ldcg16(wj + base);
        uint4 uk = ldcg16(wk + base);
        aj0 = fmaf(bflo(uj.x), a.x, aj0); aj1 = fmaf(bfhi(uj.x), a.y, aj1);
        aj0 = fmaf(bflo(uj.y), a.z, aj0); aj1 = fmaf(bfhi(uj.y), a.w, aj1);
        aj0 = fmaf(bflo(uj.z), b.x, aj0); aj1 = fmaf(bfhi(uj.z), b.y, aj1);
        aj0 = fmaf(bflo(uj.w), b.z, aj0); aj1 = fmaf(bfhi(uj.w), b.w, aj1);
        ak0 = fmaf(bflo(uk.x), a.x, ak0); ak1 = fmaf(bfhi(uk.x), a.y, ak1);
        ak0 = fmaf(bflo(uk.y), a.z, ak0); ak1 = fmaf(bfhi(uk.y), a.w, ak1);
        ak0 = fmaf(bflo(uk.z), b.x, ak0); ak1 = fmaf(bfhi(uk.z), b.y, ak1);
        ak0 = fmaf(bflo(uk.w), b.z, ak0); ak1 = fmaf(bfhi(uk.w), b.w, ak1);
    }
    return make_float2(aj0 + aj1, ak0 + ak1);
}

template <int NIT>
__device__ __forceinline__ float dotrow(const __nv_bfloat16* __restrict__ w,
                                        const float* __restrict__ v, int lane)
{
    float a0 = 0.f, a1 = 0.f;
#pragma unroll 4
    for (int it = 0; it < NIT; it++) {
        int base = it * 256 + lane * 8;
        float4 a = *(const float4*)(v + swz(base));
        float4 b = *(const float4*)(v + swz(base + 4));
        uint4 u = ldcg16(w + base);
        a0 = fmaf(bflo(u.x), a.x, a0); a1 = fmaf(bfhi(u.x), a.y, a1);
        a0 = fmaf(bflo(u.y), a.z, a0); a1 = fmaf(bfhi(u.y), a.w, a1);
        a0 = fmaf(bflo(u.z), b.x, a0); a1 = fmaf(bfhi(u.z), b.y, a1);
        a0 = fmaf(bflo(u.w), b.z, a0); a1 = fmaf(bfhi(u.w), b.w, a1);
    }
    return a0 + a1;
}

__device__ __forceinline__ float sigm(float z) { return 1.f / (1.f + __expf(-z)); }

// monotonic-counter grid barrier (all CTAs resident: grid=148)
__device__ __forceinline__ void gsync(unsigned& target)
{
    __syncthreads();
    if (threadIdx.x == 0) {
        __threadfence();
        atomicAdd(&g_bar, 1u);
        target += NCTA;
        unsigned v;
        do {
            asm volatile("ld.acquire.gpu.u32 %0, [%1];" : "=r"(v) : "l"(&g_bar) : "memory");
        } while (v < target);
    }
    __syncthreads();
}

// ---------------- persistent RNN kernel ----------------
__global__ __launch_bounds__(1024, 1) void rnn_kernel(
    const float* __restrict__ X,
    const float* __restrict__ b1,  const float* __restrict__ J1b, const float* __restrict__ K1b,
    const float* __restrict__ J2b, const float* __restrict__ K2b, const float* __restrict__ b2,
    float* __restrict__ Y)
{
    // disjoint per-phase activation buffers (38 KB static; L1D keeps ~190 KB)
    __shared__ __align__(16) float svA[3072];  // P1: [a(512); out(512); h1_old(2048)]
    __shared__ __align__(16) float svB[4096];  // P2: [h1_new(2048); h2_old(2048)]
    __shared__ __align__(16) float svC[2560];  // P3: [h2_new(2048); x_next(512)]

    const int tid  = threadIdx.x;
    const int lane = tid & 31;
    const int wid  = tid >> 5;
    const int cta  = blockIdx.x;
    const int r    = wid * NCTA + cta;   // global work index for this warp
    unsigned target = 0;

    // per-warp hoisted biases + row pointers
    float j1b = 0.f, k1b = 0.f, j2b = 0.f, k2b = 0.f, b3 = 0.f;
    const __nv_bfloat16 *pJ1 = nullptr, *pK1 = nullptr, *pJ2 = nullptr, *pK2 = nullptr, *pP3 = nullptr;
    if (r < 2048) {
        j1b = J1b[r]; k1b = K1b[r]; j2b = J2b[r]; k2b = K2b[r];
        pJ1 = &g_J1t[(size_t)r * 3072]; pK1 = &g_K1t[(size_t)r * 3072];
        pJ2 = &g_J2t[(size_t)r * 4096]; pK2 = &g_K2t[(size_t)r * 4096];
    }
    if (r < 512)            { b3 = b2[r];       pP3 = &g_W2t[(size_t)r * 2048]; }
    else if (r < 1024)      { b3 = b1[r - 512]; pP3 = &g_W1t[(size_t)(r - 512) * 2560]; }

    // ---- prologue: svC = [0(2048); X0(512)]; svA.h1_old = 0; a0 = b1 + W1^T [0;x0]
    {
        float4 z4 = make_float4(0.f, 0.f, 0.f, 0.f);
        if (tid < 512) {
            *(float4*)&svC[swz(tid * 4)] = z4;                  // h2 part = 0 (2048 floats)
            *(float4*)&svA[swz(1024 + tid * 4)] = z4;           // h1_old = 0 (2048 floats)
        }
        if (tid < 128) {
            int i = tid * 4;
            *(float4*)&svC[swz(2048 + i)] = *(const float4*)&X[i];  // x0 (512 floats)
        }
    }
    __syncthreads();
    if (r < 512) {
        float acc = dotrow<10>(&g_W1t[(size_t)r * 2560], svC, lane);
        acc = wredsum(acc);
        if (lane == 0) g_a[r] = acc + b1[r];
    }
    gsync(target);

    for (int t = 0; t < TSTEPS; t++) {
        const int p = t & 1;

        // ---- phase 1: late-fill a|out, dot J1/K1 -> h1_new; then early-fill svB.h2_old
        if (tid < 128) {
            int i = tid * 4;
            *(float4*)&svA[swz(i)] = __ldcg((const float4*)&g_a[i]);
        } else if (tid < 256) {
            int i = (tid - 128) * 4;
            *(float4*)&svA[swz(512 + i)] = __ldcg((const float4*)&g_out[i]);
        }
        __syncthreads();
        if (r < 2048) {
            float2 zz = dotrow2<12>(pJ1, pK1, svA, lane);
            float zj = wredsum(zz.x);
            float zk = wredsum(zz.y);
            if (lane == 0) {
                float j = sigm(zj + j1b);
                float k = sigm(zk + k1b);
                float h = svA[swz(1024 + r)];
                g_h1[p ^ 1][r] = fmaf(j, 1.f - h, (1.f - k) * h);
            }
        }
        if (tid < 512) {  // early-fill: h2_old (written last step) into svB hi half
            int i = tid * 4;
            *(float4*)&svB[swz(2048 + i)] = __ldcg((const float4*)&g_h2[p][i]);
        }
        gsync(target);

        // ---- phase 2: late-fill h1_new, dot J2/K2 -> h2_new; then early-fill svC.x_next
        if (tid < 512) {
            int i = tid * 4;
            *(float4*)&svB[swz(i)] = __ldcg((const float4*)&g_h1[p ^ 1][i]);
        }
        __syncthreads();
        if (r < 2048) {
            float2 zz = dotrow2<16>(pJ2, pK2, svB, lane);
            float zj = wredsum(zz.x);
            float zk = wredsum(zz.y);
            if (lane == 0) {
                float j = sigm(zj + j2b);
                float k = sigm(zk + k2b);
                float h = svB[swz(2048 + r)];
                g_h2[p ^ 1][r] = fmaf(j, 1.f - h, (1.f - k) * h);
            }
        }
        const bool hasNext = (t + 1) < TSTEPS;
        if (hasNext && tid < 128) {  // early-fill: x_{t+1}
            int i = tid * 4;
            *(float4*)&svC[swz(2048 + i)] = *(const float4*)&X[(size_t)(t + 1) * 512 + i];
        }
        gsync(target);

        // ---- phase 3: late-fill h2_new, dot W2 (out) + W1 (a_next); early-fill svA.h1_old
        if (tid < 512) {
            int i = tid * 4;
            *(float4*)&svC[swz(i)] = __ldcg((const float4*)&g_h2[p ^ 1][i]);
        }
        __syncthreads();
        if (r < 512) {
            float acc = dotrow<8>(pP3, svC, lane);
            acc = wredsum(acc);
            if (lane == 0) {
                float s = sigm(acc + b3);
                g_out[r] = s;
                Y[(size_t)t * 512 + r] = s;
            }
        } else if (r < 1024 && hasNext) {
            float acc = dotrow<10>(pP3, svC, lane);
            acc = wredsum(acc);
            if (lane == 0) g_a[r - 512] = acc + b3;
        }
        if (tid < 512) {  // early-fill: h1 state for next step's P1
            int i = tid * 4;
            *(float4*)&svA[swz(1024 + i)] = __ldcg((const float4*)&g_h1[p ^ 1][i]);
        }
        gsync(target);
    }
}

// ---------------- launch ----------------
extern "C" void kernel_launch(void* const* d_in, const int* in_sizes, int n_in,
                              void* d_out, int out_size)
{
    (void)in_sizes; (void)n_in; (void)out_size;
    const float* X   = (const float*)d_in[0];
    const float* W1  = (const float*)d_in[1];
    const float* b1  = (const float*)d_in[2];
    const float* J1W = (const float*)d_in[3];
    const float* J1b = (const float*)d_in[4];
    const float* K1W = (const float*)d_in[5];
    const float* K1b = (const float*)d_in[6];
    const float* J2W = (const float*)d_in[7];
    const float* J2b = (const float*)d_in[8];
    const float* K2W = (const float*)d_in[9];
    const float* K2b = (const float*)d_in[10];
    const float* W2  = (const float*)d_in[11];
    const float* b2  = (const float*)d_in[12];
    float* Y = (float*)d_out;

    dim3 tb(32, 8);
    transpose_convert<<<dim3(512 / 32, 2560 / 32), tb>>>(W1, 0, 2560, 512);
    transpose_convert<<<dim3(2048 / 32, 3072 / 32), tb>>>(J1W, 1, 3072, 2048);
    transpose_convert<<<dim3(2048 / 32, 3072 / 32), tb>>>(K1W, 2, 3072, 2048);
    transpose_convert<<<dim3(2048 / 32, 4096 / 32), tb>>>(J2W, 3, 4096, 2048);
    transpose_convert<<<dim3(2048 / 32, 4096 / 32), tb>>>(K2W, 4, 4096, 2048);
    transpose_convert<<<dim3(512 / 32, 2048 / 32), tb>>>(W2, 5, 2048, 512);
    init_state<<<2, 1024>>>();
    rnn_kernel<<<NCTA, 1024>>>(X, b1, J1b, K1b, J2b, K2b, b2, Y);
}

// round 11
// speedup vs baseline: 1.7924x; 1.0676x over previous
#include <cuda_runtime.h>
#include <cuda_bf16.h>
#include <cstdint>
#include <cstddef>

#define NCTA    148
#define TSTEPS  2048
#define NTHREAD 512
#define NCACHE2 11                         // cached (J2,K2) row-pairs per CTA
#define CACHE_BYTES (NCACHE2 * 16384)      // 176 KB dynamic smem

// ---------------- static device storage (allowed scratch) ----------------
__device__ __align__(16) __nv_bfloat16 g_W1t[(size_t)512  * 2560]; // [out][in] in=[h2(2048);x(512)]
__device__ __align__(16) __nv_bfloat16 g_J1t[(size_t)2048 * 3072];
__device__ __align__(16) __nv_bfloat16 g_K1t[(size_t)2048 * 3072];
__device__ __align__(16) __nv_bfloat16 g_J2t[(size_t)2048 * 4096];
__device__ __align__(16) __nv_bfloat16 g_K2t[(size_t)2048 * 4096];
__device__ __align__(16) __nv_bfloat16 g_W2t[(size_t)512  * 2048];

__device__ float g_a[512];
__device__ float g_out[512];
__device__ float g_h1[2][2048];
__device__ float g_h2[2][2048];
__device__ unsigned g_bar;

// ---------------- merged transpose + fp32->bf16 convert (ONE launch) ----------------
__global__ void transpose_all(const float* __restrict__ W1, const float* __restrict__ J1W,
                              const float* __restrict__ K1W, const float* __restrict__ J2W,
                              const float* __restrict__ K2W, const float* __restrict__ W2)
{
    __shared__ float tile[32][33];
    int id = blockIdx.x;
    const float* src; __nv_bfloat16* dst; int fi, fo, base;
    if      (id < 1280)  { src = W1;  dst = g_W1t; fi = 2560; fo = 512;  base = 0; }
    else if (id < 7424)  { src = J1W; dst = g_J1t; fi = 3072; fo = 2048; base = 1280; }
    else if (id < 13568) { src = K1W; dst = g_K1t; fi = 3072; fo = 2048; base = 7424; }
    else if (id < 21760) { src = J2W; dst = g_J2t; fi = 4096; fo = 2048; base = 13568; }
    else if (id < 29952) { src = K2W; dst = g_K2t; fi = 4096; fo = 2048; base = 21760; }
    else                 { src = W2;  dst = g_W2t; fi = 2048; fo = 512;  base = 29952; }
    int lid = id - base;
    int ntx = fo / 32;                    // tiles along fan_out
    int o0 = (lid % ntx) * 32;
    int i0 = (lid / ntx) * 32;
    for (int r = threadIdx.y; r < 32; r += 8)
        tile[r][threadIdx.x] = src[(size_t)(i0 + r) * fo + o0 + threadIdx.x];
    __syncthreads();
    for (int r = threadIdx.y; r < 32; r += 8)
        dst[(size_t)(o0 + r) * fi + i0 + threadIdx.x] = __float2bfloat16(tile[threadIdx.x][r]);
}

__global__ void init_state()
{
    int i = blockIdx.x * blockDim.x + threadIdx.x;
    if (i == 0) g_bar = 0u;
    if (i < 512) g_out[i] = 0.f;
    if (i < 2048) { g_h1[0][i] = 0.f; g_h2[0][i] = 0.f; }
}

// ---------------- helpers ----------------
__device__ __forceinline__ float bflo(unsigned w) { return __uint_as_float(w << 16); }
__device__ __forceinline__ float bfhi(unsigned w) { return __uint_as_float(w & 0xffff0000u); }

// 16B-granular XOR swizzle (conflict-free LDS.128 for lane*32B pattern)
__device__ __forceinline__ int swz(int i) { return i ^ (((i >> 5) & 1) << 2); }

__device__ __forceinline__ float wredsum(float a)
{
#pragma unroll
    for (int o = 16; o > 0; o >>= 1) a += __shfl_xor_sync(0xffffffffu, a, o);
    return a;
}

__device__ __forceinline__ uint4 ldcg16(const __nv_bfloat16* p)
{
    return __ldcg((const uint4*)p);
}

// dual-row dot, weights streamed from GMEM via LDG.cg (L2-only)
template <int NIT>
__device__ __forceinline__ float2 dotrow2(const __nv_bfloat16* __restrict__ wj,
                                          const __nv_bfloat16* __restrict__ wk,
                                          const float* __restrict__ v, int lane)
{
    float aj0 = 0.f, aj1 = 0.f, ak0 = 0.f, ak1 = 0.f;
#pragma unroll 4
    for (int it = 0; it < NIT; it++) {
        int base = it * 256 + lane * 8;
        float4 a = *(const float4*)(v + swz(base));
        float4 b = *(const float4*)(v + swz(base + 4));
        uint4 uj = ldcg16(wj + base);
        uint4 uk = ldcg16(wk + base);
        aj0 = fmaf(bflo(uj.x), a.x, aj0); aj1 = fmaf(bfhi(uj.x), a.y, aj1);
        aj0 = fmaf(bflo(uj.y), a.z, aj0); aj1 = fmaf(bfhi(uj.y), a.w, aj1);
        aj0 = fmaf(bflo(uj.z), b.x, aj0); aj1 = fmaf(bfhi(uj.z), b.y, aj1);
        aj0 = fmaf(bflo(uj.w), b.z, aj0); aj1 = fmaf(bfhi(uj.w), b.w, aj1);
        ak0 = fmaf(bflo(uk.x), a.x, ak0); ak1 = fmaf(bfhi(uk.x), a.y, ak1);
        ak0 = fmaf(bflo(uk.y), a.z, ak0); ak1 = fmaf(bfhi(uk.y), a.w, ak1);
        ak0 = fmaf(bflo(uk.z), b.x, ak0); ak1 = fmaf(bfhi(uk.z), b.y, ak1);
        ak0 = fmaf(bflo(uk.w), b.z, ak0); ak1 = fmaf(bfhi(uk.w), b.w, ak1);
    }
    return make_float2(aj0 + aj1, ak0 + ak1);
}

// dual-row dot, weights from SMEM via explicit ld.shared.v4 (guaranteed LDS.128)
template <int NIT>
__device__ __forceinline__ float2 dotrow2_smem(unsigned wj, unsigned wk,
                                               const float* __restrict__ v, int lane)
{
    float aj0 = 0.f, aj1 = 0.f, ak0 = 0.f, ak1 = 0.f;
#pragma unroll 4
    for (int it = 0; it < NIT; it++) {
        int base = it * 256 + lane * 8;
        float4 a = *(const float4*)(v + swz(base));
        float4 b = *(const float4*)(v + swz(base + 4));
        unsigned j0, j1, j2, j3, k0, k1, k2, k3;
        asm("ld.shared.v4.b32 {%0,%1,%2,%3}, [%4];"
            : "=r"(j0), "=r"(j1), "=r"(j2), "=r"(j3) : "r"(wj + (unsigned)base * 2));
        asm("ld.shared.v4.b32 {%0,%1,%2,%3}, [%4];"
            : "=r"(k0), "=r"(k1), "=r"(k2), "=r"(k3) : "r"(wk + (unsigned)base * 2));
        aj0 = fmaf(bflo(j0), a.x, aj0); aj1 = fmaf(bfhi(j0), a.y, aj1);
        aj0 = fmaf(bflo(j1), a.z, aj0); aj1 = fmaf(bfhi(j1), a.w, aj1);
        aj0 = fmaf(bflo(j2), b.x, aj0); aj1 = fmaf(bfhi(j2), b.y, aj1);
        aj0 = fmaf(bflo(j3), b.z, aj0); aj1 = fmaf(bfhi(j3), b.w, aj1);
        ak0 = fmaf(bflo(k0), a.x, ak0); ak1 = fmaf(bfhi(k0), a.y, ak1);
        ak0 = fmaf(bflo(k1), a.z, ak0); ak1 = fmaf(bfhi(k1), a.w, ak1);
        ak0 = fmaf(bflo(k2), b.x, ak0); ak1 = fmaf(bfhi(k2), b.y, ak1);
        ak0 = fmaf(bflo(k3), b.z, ak0); ak1 = fmaf(bfhi(k3), b.w, ak1);
    }
    return make_float2(aj0 + aj1, ak0 + ak1);
}

template <int NIT>
__device__ __forceinline__ float dotrow(const __nv_bfloat16* __restrict__ w,
                                        const float* __restrict__ v, int lane)
{
    float a0 = 0.f, a1 = 0.f;
#pragma unroll 4
    for (int it = 0; it < NIT; it++) {
        int base = it * 256 + lane * 8;
        float4 a = *(const float4*)(v + swz(base));
        float4 b = *(const float4*)(v + swz(base + 4));
        uint4 u = ldcg16(w + base);
        a0 = fmaf(bflo(u.x), a.x, a0); a1 = fmaf(bfhi(u.x), a.y, a1);
        a0 = fmaf(bflo(u.y), a.z, a0); a1 = fmaf(bfhi(u.y), a.w, a1);
        a0 = fmaf(bflo(u.z), b.x, a0); a1 = fmaf(bfhi(u.z), b.y, a1);
        a0 = fmaf(bflo(u.w), b.z, a0); a1 = fmaf(bfhi(u.w), b.w, a1);
    }
    return a0 + a1;
}

__device__ __forceinline__ float sigm(float z) { return 1.f / (1.f + __expf(-z)); }

// monotonic-counter grid barrier (all CTAs resident: grid=148)
__device__ __forceinline__ void gsync(unsigned& target)
{
    __syncthreads();
    if (threadIdx.x == 0) {
        __threadfence();
        atomicAdd(&g_bar, 1u);
        target += NCTA;
        unsigned v;
        do {
            asm volatile("ld.acquire.gpu.u32 %0, [%1];" : "=r"(v) : "l"(&g_bar) : "memory");
        } while (v < target);
    }
    __syncthreads();
}

// ---------------- persistent RNN kernel ----------------
__global__ __launch_bounds__(NTHREAD, 1) void rnn_kernel(
    const float* __restrict__ X,
    const float* __restrict__ b1,  const float* __restrict__ J1b, const float* __restrict__ K1b,
    const float* __restrict__ J2b, const float* __restrict__ K2b, const float* __restrict__ b2,
    float* __restrict__ Y)
{
    // disjoint per-phase activation buffers (≈38 KB static)
    __shared__ __align__(16) float svA[3072];  // P1: [a(512); out(512); h1_old(2048)]
    __shared__ __align__(16) float svB[4096];  // P2: [h1_new(2048); h2_old(2048)]
    __shared__ __align__(16) float svC[2560];  // P3: [h2_new(2048); x_next(512)]
    extern __shared__ __align__(16) unsigned char wcache[];  // 176 KB: 11 x [J2row 8KB | K2row 8KB]

    const int tid  = threadIdx.x;
    const int lane = tid & 31;
    const int wid  = tid >> 5;
    const int cta  = blockIdx.x;
    const int r    = wid * NCTA + cta;   // global work index for this warp
    unsigned target = 0;
    const unsigned wc_base = (unsigned)__cvta_generic_to_shared(wcache);

    // per-warp hoisted biases + row pointers
    float j1b = 0.f, k1b = 0.f, j2b = 0.f, k2b = 0.f, b3 = 0.f;
    const __nv_bfloat16 *pJ1 = nullptr, *pK1 = nullptr, *pJ2 = nullptr, *pK2 = nullptr, *pP3 = nullptr;
    if (r < 2048) {
        j1b = J1b[r]; k1b = K1b[r]; j2b = J2b[r]; k2b = K2b[r];
        pJ1 = &g_J1t[(size_t)r * 3072]; pK1 = &g_K1t[(size_t)r * 3072];
        pJ2 = &g_J2t[(size_t)r * 4096]; pK2 = &g_K2t[(size_t)r * 4096];
    }
    if (r < 512)            { b3 = b2[r];       pP3 = &g_W2t[(size_t)r * 2048]; }
    else if (r < 1024)      { b3 = b1[r - 512]; pP3 = &g_W1t[(size_t)(r - 512) * 2560]; }

    // ---- fill the SMEM weight cache (once): pairs for rows q*148+cta, q=0..10
    for (int q = 0; q < NCACHE2; q++) {
        const size_t row = (size_t)(q * NCTA + cta) * 4096;
        uint4* dJ = (uint4*)(wcache + q * 16384);
        uint4* dK = (uint4*)(wcache + q * 16384 + 8192);
        dJ[tid] = __ldcg((const uint4*)&g_J2t[row] + tid);
        dK[tid] = __ldcg((const uint4*)&g_K2t[row] + tid);
    }

    // ---- prologue: svC = [0(2048); X0(512)]; svA.h1_old = 0; a0 = b1 + W1^T [0;x0]
    {
        float4 z4 = make_float4(0.f, 0.f, 0.f, 0.f);
        *(float4*)&svC[swz(tid * 4)] = z4;                      // h2 part = 0 (2048 floats)
        *(float4*)&svA[swz(1024 + tid * 4)] = z4;               // h1_old = 0 (2048 floats)
        if (tid < 128) {
            int i = tid * 4;
            *(float4*)&svC[swz(2048 + i)] = __ldcg((const float4*)&X[i]);   // x0
        }
    }
    __syncthreads();
    if (r < 512) {
        float acc = dotrow<10>(&g_W1t[(size_t)r * 2560], svC, lane);
        acc = wredsum(acc);
        if (lane == 0) g_a[r] = acc + b1[r];
    }
    gsync(target);

    for (int t = 0; t < TSTEPS; t++) {
        const int p = t & 1;

        // ---- phase 1: late-fill a|out, dot J1/K1 -> h1_new; then early-fill svB.h2_old
        if (tid < 128) {
            int i = tid * 4;
            *(float4*)&svA[swz(i)] = __ldcg((const float4*)&g_a[i]);
        } else if (tid < 256) {
            int i = (tid - 128) * 4;
            *(float4*)&svA[swz(512 + i)] = __ldcg((const float4*)&g_out[i]);
        }
        __syncthreads();
        if (r < 2048) {
            float2 zz = dotrow2<12>(pJ1, pK1, svA, lane);
            float zj = wredsum(zz.x);
            float zk = wredsum(zz.y);
            if (lane == 0) {
                float j = sigm(zj + j1b);
                float k = sigm(zk + k1b);
                float h = svA[swz(1024 + r)];
                g_h1[p ^ 1][r] = fmaf(j, 1.f - h, (1.f - k) * h);
            }
        }
        {   // early-fill: h2_old (written last step) into svB hi half
            int i = tid * 4;
            *(float4*)&svB[swz(2048 + i)] = __ldcg((const float4*)&g_h2[p][i]);
        }
        gsync(target);

        // ---- phase 2: late-fill h1_new, dot J2/K2 -> h2_new; then early-fill svC.x_next
        {
            int i = tid * 4;
            *(float4*)&svB[swz(i)] = __ldcg((const float4*)&g_h1[p ^ 1][i]);
        }
        __syncthreads();
        if (r < 2048) {
            float2 zz;
            if (wid < NCACHE2) {
                unsigned wj = wc_base + (unsigned)wid * 16384u;
                zz = dotrow2_smem<16>(wj, wj + 8192u, svB, lane);
            } else {
                zz = dotrow2<16>(pJ2, pK2, svB, lane);
            }
            float zj = wredsum(zz.x);
            float zk = wredsum(zz.y);
            if (lane == 0) {
                float j = sigm(zj + j2b);
                float k = sigm(zk + k2b);
                float h = svB[swz(2048 + r)];
                g_h2[p ^ 1][r] = fmaf(j, 1.f - h, (1.f - k) * h);
            }
        }
        const bool hasNext = (t + 1) < TSTEPS;
        if (hasNext && tid < 128) {  // early-fill: x_{t+1}
            int i = tid * 4;
            *(float4*)&svC[swz(2048 + i)] = __ldcg((const float4*)&X[(size_t)(t + 1) * 512 + i]);
        }
        gsync(target);

        // ---- phase 3: late-fill h2_new, dot W2 (out) + W1 (a_next); early-fill svA.h1_old
        {
            int i = tid * 4;
            *(float4*)&svC[swz(i)] = __ldcg((const float4*)&g_h2[p ^ 1][i]);
        }
        __syncthreads();
        if (r < 512) {
            float acc = dotrow<8>(pP3, svC, lane);
            acc = wredsum(acc);
            if (lane == 0) {
                float s = sigm(acc + b3);
                g_out[r] = s;
                Y[(size_t)t * 512 + r] = s;
            }
        } else if (r < 1024 && hasNext) {
            float acc = dotrow<10>(pP3, svC, lane);
            acc = wredsum(acc);
            if (lane == 0) g_a[r - 512] = acc + b3;
        }
        {   // early-fill: h1 state for next step's P1
            int i = tid * 4;
            *(float4*)&svA[swz(1024 + i)] = __ldcg((const float4*)&g_h1[p ^ 1][i]);
        }
        gsync(target);
    }
}

// ---------------- launch ----------------
extern "C" void kernel_launch(void* const* d_in, const int* in_sizes, int n_in,
                              void* d_out, int out_size)
{
    (void)in_sizes; (void)n_in; (void)out_size;
    const float* X   = (const float*)d_in[0];
    const float* W1  = (const float*)d_in[1];
    const float* b1  = (const float*)d_in[2];
    const float* J1W = (const float*)d_in[3];
    const float* J1b = (const float*)d_in[4];
    const float* K1W = (const float*)d_in[5];
    const float* K1b = (const float*)d_in[6];
    const float* J2W = (const float*)d_in[7];
    const float* J2b = (const float*)d_in[8];
    const float* K2W = (const float*)d_in[9];
    const float* K2b = (const float*)d_in[10];
    const float* W2  = (const float*)d_in[11];
    const float* b2  = (const float*)d_in[12];
    float* Y = (float*)d_out;

    cudaFuncSetAttribute(rnn_kernel, cudaFuncAttributeMaxDynamicSharedMemorySize, CACHE_BYTES);

    transpose_all<<<30976, dim3(32, 8)>>>(W1, J1W, K1W, J2W, K2W, W2);
    init_state<<<2, 1024>>>();
    rnn_kernel<<<NCTA, NTHREAD, CACHE_BYTES>>>(X, b1, J1b, K1b, J2b, K2b, b2, Y);
}

// round 17
// speedup vs baseline: 1.8062x; 1.0077x over previous
#include <cuda_runtime.h>
#include <cuda_bf16.h>
#include <cstdint>
#include <cstddef>

#define NCTA    148
#define TSTEPS  2048
#define NTHREAD 512
#define NCACHE2 11                         // cached (J2,K2) row-pairs per CTA
#define CACHE_BYTES (NCACHE2 * 16384)      // 176 KB dynamic smem

// ---------------- static device storage (allowed scratch) ----------------
__device__ __align__(16) __nv_bfloat16 g_W1t[(size_t)512  * 2560]; // [out][in] in=[h2(2048);x(512)]
__device__ __align__(16) __nv_bfloat16 g_J1t[(size_t)2048 * 3072];
__device__ __align__(16) __nv_bfloat16 g_K1t[(size_t)2048 * 3072];
__device__ __align__(16) __nv_bfloat16 g_J2t[(size_t)2048 * 4096];
__device__ __align__(16) __nv_bfloat16 g_K2t[(size_t)2048 * 4096];
__device__ __align__(16) __nv_bfloat16 g_W2t[(size_t)512  * 2048];

__device__ float g_a[512];
__device__ float g_out[512];
__device__ float g_h1[2][2048];
__device__ float g_h2[2][2048];
__device__ unsigned g_bar;

// ---------------- merged transpose + fp32->bf16 convert (ONE launch) ----------------
__global__ void transpose_all(const float* __restrict__ W1, const float* __restrict__ J1W,
                              const float* __restrict__ K1W, const float* __restrict__ J2W,
                              const float* __restrict__ K2W, const float* __restrict__ W2)
{
    __shared__ float tile[32][33];
    int id = blockIdx.x;
    const float* src; __nv_bfloat16* dst; int fi, fo, base;
    if      (id < 1280)  { src = W1;  dst = g_W1t; fi = 2560; fo = 512;  base = 0; }
    else if (id < 7424)  { src = J1W; dst = g_J1t; fi = 3072; fo = 2048; base = 1280; }
    else if (id < 13568) { src = K1W; dst = g_K1t; fi = 3072; fo = 2048; base = 7424; }
    else if (id < 21760) { src = J2W; dst = g_J2t; fi = 4096; fo = 2048; base = 13568; }
    else if (id < 29952) { src = K2W; dst = g_K2t; fi = 4096; fo = 2048; base = 21760; }
    else                 { src = W2;  dst = g_W2t; fi = 2048; fo = 512;  base = 29952; }
    int lid = id - base;
    int ntx = fo / 32;                    // tiles along fan_out
    int o0 = (lid % ntx) * 32;
    int i0 = (lid / ntx) * 32;
    for (int r = threadIdx.y; r < 32; r += 8)
        tile[r][threadIdx.x] = src[(size_t)(i0 + r) * fo + o0 + threadIdx.x];
    __syncthreads();
    for (int r = threadIdx.y; r < 32; r += 8)
        dst[(size_t)(o0 + r) * fi + i0 + threadIdx.x] = __float2bfloat16(tile[threadIdx.x][r]);
}

__global__ void init_state()
{
    int i = blockIdx.x * blockDim.x + threadIdx.x;
    if (i == 0) g_bar = 0u;
    if (i < 512) g_out[i] = 0.f;
    if (i < 2048) { g_h1[0][i] = 0.f; g_h2[0][i] = 0.f; }
}

// ---------------- helpers ----------------
__device__ __forceinline__ float bflo(unsigned w) { return __uint_as_float(w << 16); }
__device__ __forceinline__ float bfhi(unsigned w) { return __uint_as_float(w & 0xffff0000u); }

// 16B-granular XOR swizzle (conflict-free LDS.128 for lane*32B pattern)
__device__ __forceinline__ int swz(int i) { return i ^ (((i >> 5) & 1) << 2); }

__device__ __forceinline__ float wredsum(float a)
{
#pragma unroll
    for (int o = 16; o > 0; o >>= 1) a += __shfl_xor_sync(0xffffffffu, a, o);
    return a;
}

__device__ __forceinline__ uint4 ldcg16(const __nv_bfloat16* p)
{
    return __ldcg((const uint4*)p);
}

// dual-row dot, weights streamed from GMEM via LDG.cg (L2-only).
// Depth-4 register prefetch ring: 8 independent 16B loads in flight per warp,
// converting the per-iteration exposed L2 latency (~340cyc, MLP=2) into
// an issue-bound loop (~160cyc/iter).
template <int NIT>
__device__ __forceinline__ float2 dotrow2(const __nv_bfloat16* __restrict__ wj,
                                          const __nv_bfloat16* __restrict__ wk,
                                          const float* __restrict__ v, int lane)
{
    constexpr int PF = 4;
    uint4 bj[PF], bk[PF];
#pragma unroll
    for (int i = 0; i < PF; i++) {
        bj[i] = ldcg16(wj + i * 256 + lane * 8);
        bk[i] = ldcg16(wk + i * 256 + lane * 8);
    }
    float aj0 = 0.f, aj1 = 0.f, ak0 = 0.f, ak1 = 0.f;
#pragma unroll
    for (int it = 0; it < NIT; it++) {
        int base = it * 256 + lane * 8;
        uint4 uj = bj[it % PF];
        uint4 uk = bk[it % PF];
        if (it + PF < NIT) {
            bj[it % PF] = ldcg16(wj + (it + PF) * 256 + lane * 8);
            bk[it % PF] = ldcg16(wk + (it + PF) * 256 + lane * 8);
        }
        float4 a = *(const float4*)(v + swz(base));
        float4 b = *(const float4*)(v + swz(base + 4));
        aj0 = fmaf(bflo(uj.x), a.x, aj0); aj1 = fmaf(bfhi(uj.x), a.y, aj1);
        aj0 = fmaf(bflo(uj.y), a.z, aj0); aj1 = fmaf(bfhi(uj.y), a.w, aj1);
        aj0 = fmaf(bflo(uj.z), b.x, aj0); aj1 = fmaf(bfhi(uj.z), b.y, aj1);
        aj0 = fmaf(bflo(uj.w), b.z, aj0); aj1 = fmaf(bfhi(uj.w), b.w, aj1);
        ak0 = fmaf(bflo(uk.x), a.x, ak0); ak1 = fmaf(bfhi(uk.x), a.y, ak1);
        ak0 = fmaf(bflo(uk.y), a.z, ak0); ak1 = fmaf(bfhi(uk.y), a.w, ak1);
        ak0 = fmaf(bflo(uk.z), b.x, ak0); ak1 = fmaf(bfhi(uk.z), b.y, ak1);
        ak0 = fmaf(bflo(uk.w), b.z, ak0); ak1 = fmaf(bfhi(uk.w), b.w, ak1);
    }
    return make_float2(aj0 + aj1, ak0 + ak1);
}

// dual-row dot, weights from SMEM via explicit ld.shared.v4 (guaranteed LDS.128;
// 29cyc latency hidden by the scoreboard, no prefetch needed)
template <int NIT>
__device__ __forceinline__ float2 dotrow2_smem(unsigned wj, unsigned wk,
                                               const float* __restrict__ v, int lane)
{
    float aj0 = 0.f, aj1 = 0.f, ak0 = 0.f, ak1 = 0.f;
#pragma unroll 4
    for (int it = 0; it < NIT; it++) {
        int base = it * 256 + lane * 8;
        float4 a = *(const float4*)(v + swz(base));
        float4 b = *(const float4*)(v + swz(base + 4));
        unsigned j0, j1, j2, j3, k0, k1, k2, k3;
        asm("ld.shared.v4.b32 {%0,%1,%2,%3}, [%4];"
            : "=r"(j0), "=r"(j1), "=r"(j2), "=r"(j3) : "r"(wj + (unsigned)base * 2));
        asm("ld.shared.v4.b32 {%0,%1,%2,%3}, [%4];"
            : "=r"(k0), "=r"(k1), "=r"(k2), "=r"(k3) : "r"(wk + (unsigned)base * 2));
        aj0 = fmaf(bflo(j0), a.x, aj0); aj1 = fmaf(bfhi(j0), a.y, aj1);
        aj0 = fmaf(bflo(j1), a.z, aj0); aj1 = fmaf(bfhi(j1), a.w, aj1);
        aj0 = fmaf(bflo(j2), b.x, aj0); aj1 = fmaf(bfhi(j2), b.y, aj1);
        aj0 = fmaf(bflo(j3), b.z, aj0); aj1 = fmaf(bfhi(j3), b.w, aj1);
        ak0 = fmaf(bflo(k0), a.x, ak0); ak1 = fmaf(bfhi(k0), a.y, ak1);
        ak0 = fmaf(bflo(k1), a.z, ak0); ak1 = fmaf(bfhi(k1), a.w, ak1);
        ak0 = fmaf(bflo(k2), b.x, ak0); ak1 = fmaf(bfhi(k2), b.y, ak1);
        ak0 = fmaf(bflo(k3), b.z, ak0); ak1 = fmaf(bfhi(k3), b.w, ak1);
    }
    return make_float2(aj0 + aj1, ak0 + ak1);
}

// single-row dot with the same depth-4 prefetch ring
template <int NIT>
__device__ __forceinline__ float dotrow(const __nv_bfloat16* __restrict__ w,
                                        const float* __restrict__ v, int lane)
{
    constexpr int PF = 4;
    uint4 bw[PF];
#pragma unroll
    for (int i = 0; i < PF; i++) bw[i] = ldcg16(w + i * 256 + lane * 8);
    float a0 = 0.f, a1 = 0.f;
#pragma unroll
    for (int it = 0; it < NIT; it++) {
        int base = it * 256 + lane * 8;
        uint4 u = bw[it % PF];
        if (it + PF < NIT) bw[it % PF] = ldcg16(w + (it + PF) * 256 + lane * 8);
        float4 a = *(const float4*)(v + swz(base));
        float4 b = *(const float4*)(v + swz(base + 4));
        a0 = fmaf(bflo(u.x), a.x, a0); a1 = fmaf(bfhi(u.x), a.y, a1);
        a0 = fmaf(bflo(u.y), a.z, a0); a1 = fmaf(bfhi(u.y), a.w, a1);
        a0 = fmaf(bflo(u.z), b.x, a0); a1 = fmaf(bfhi(u.z), b.y, a1);
        a0 = fmaf(bflo(u.w), b.z, a0); a1 = fmaf(bfhi(u.w), b.w, a1);
    }
    return a0 + a1;
}

__device__ __forceinline__ float sigm(float z) { return 1.f / (1.f + __expf(-z)); }

// monotonic-counter grid barrier (all CTAs resident: grid=148)
__device__ __forceinline__ void gsync(unsigned& target)
{
    __syncthreads();
    if (threadIdx.x == 0) {
        __threadfence();
        atomicAdd(&g_bar, 1u);
        target += NCTA;
        unsigned v;
        do {
            asm volatile("ld.acquire.gpu.u32 %0, [%1];" : "=r"(v) : "l"(&g_bar) : "memory");
        } while (v < target);
    }
    __syncthreads();
}

// ---------------- persistent RNN kernel ----------------
__global__ __launch_bounds__(NTHREAD, 1) void rnn_kernel(
    const float* __restrict__ X,
    const float* __restrict__ b1,  const float* __restrict__ J1b, const float* __restrict__ K1b,
    const float* __restrict__ J2b, const float* __restrict__ K2b, const float* __restrict__ b2,
    float* __restrict__ Y)
{
    // disjoint per-phase activation buffers (≈38 KB static)
    __shared__ __align__(16) float svA[3072];  // P1: [a(512); out(512); h1_old(2048)]
    __shared__ __align__(16) float svB[4096];  // P2: [h1_new(2048); h2_old(2048)]
    __shared__ __align__(16) float svC[2560];  // P3: [h2_new(2048); x_next(512)]
    extern __shared__ __align__(16) unsigned char wcache[];  // 176 KB: 11 x [J2row 8KB | K2row 8KB]

    const int tid  = threadIdx.x;
    const int lane = tid & 31;
    const int wid  = tid >> 5;
    const int cta  = blockIdx.x;
    const int r    = wid * NCTA + cta;   // global work index for this warp
    unsigned target = 0;
    const unsigned wc_base = (unsigned)__cvta_generic_to_shared(wcache);

    // per-warp hoisted biases + row pointers
    float j1b = 0.f, k1b = 0.f, j2b = 0.f, k2b = 0.f, b3 = 0.f;
    const __nv_bfloat16 *pJ1 = nullptr, *pK1 = nullptr, *pJ2 = nullptr, *pK2 = nullptr, *pP3 = nullptr;
    if (r < 2048) {
        j1b = J1b[r]; k1b = K1b[r]; j2b = J2b[r]; k2b = K2b[r];
        pJ1 = &g_J1t[(size_t)r * 3072]; pK1 = &g_K1t[(size_t)r * 3072];
        pJ2 = &g_J2t[(size_t)r * 4096]; pK2 = &g_K2t[(size_t)r * 4096];
    }
    if (r < 512)            { b3 = b2[r];       pP3 = &g_W2t[(size_t)r * 2048]; }
    else if (r < 1024)      { b3 = b1[r - 512]; pP3 = &g_W1t[(size_t)(r - 512) * 2560]; }

    // ---- fill the SMEM weight cache (once): pairs for rows q*148+cta, q=0..10
    for (int q = 0; q < NCACHE2; q++) {
        const size_t row = (size_t)(q * NCTA + cta) * 4096;
        uint4* dJ = (uint4*)(wcache + q * 16384);
        uint4* dK = (uint4*)(wcache + q * 16384 + 8192);
        dJ[tid] = __ldcg((const uint4*)&g_J2t[row] + tid);
        dK[tid] = __ldcg((const uint4*)&g_K2t[row] + tid);
    }

    // ---- prologue: svC = [0(2048); X0(512)]; svA.h1_old = 0; a0 = b1 + W1^T [0;x0]
    {
        float4 z4 = make_float4(0.f, 0.f, 0.f, 0.f);
        *(float4*)&svC[swz(tid * 4)] = z4;                      // h2 part = 0 (2048 floats)
        *(float4*)&svA[swz(1024 + tid * 4)] = z4;               // h1_old = 0 (2048 floats)
        if (tid < 128) {
            int i = tid * 4;
            *(float4*)&svC[swz(2048 + i)] = __ldcg((const float4*)&X[i]);   // x0
        }
    }
    __syncthreads();
    if (r < 512) {
        float acc = dotrow<10>(&g_W1t[(size_t)r * 2560], svC, lane);
        acc = wredsum(acc);
        if (lane == 0) g_a[r] = acc + b1[r];
    }
    gsync(target);

    for (int t = 0; t < TSTEPS; t++) {
        const int p = t & 1;

        // ---- phase 1: late-fill a|out, dot J1/K1 -> h1_new; then early-fill svB.h2_old
        if (tid < 128) {
            int i = tid * 4;
            *(float4*)&svA[swz(i)] = __ldcg((const float4*)&g_a[i]);
        } else if (tid < 256) {
            int i = (tid - 128) * 4;
            *(float4*)&svA[swz(512 + i)] = __ldcg((const float4*)&g_out[i]);
        }
        __syncthreads();
        if (r < 2048) {
            float2 zz = dotrow2<12>(pJ1, pK1, svA, lane);
            float zj = wredsum(zz.x);
            float zk = wredsum(zz.y);
            if (lane == 0) {
                float j = sigm(zj + j1b);
                float k = sigm(zk + k1b);
                float h = svA[swz(1024 + r)];
                g_h1[p ^ 1][r] = fmaf(j, 1.f - h, (1.f - k) * h);
            }
        }
        {   // early-fill: h2_old (written last step) into svB hi half
            int i = tid * 4;
            *(float4*)&svB[swz(2048 + i)] = __ldcg((const float4*)&g_h2[p][i]);
        }
        gsync(target);

        // ---- phase 2: late-fill h1_new, dot J2/K2 -> h2_new; then early-fill svC.x_next
        {
            int i = tid * 4;
            *(float4*)&svB[swz(i)] = __ldcg((const float4*)&g_h1[p ^ 1][i]);
        }
        __syncthreads();
        if (r < 2048) {
            float2 zz;
            if (wid < NCACHE2) {
                unsigned wj = wc_base + (unsigned)wid * 16384u;
                zz = dotrow2_smem<16>(wj, wj + 8192u, svB, lane);
            } else {
                zz = dotrow2<16>(pJ2, pK2, svB, lane);
            }
            float zj = wredsum(zz.x);
            float zk = wredsum(zz.y);
            if (lane == 0) {
                float j = sigm(zj + j2b);
                float k = sigm(zk + k2b);
                float h = svB[swz(2048 + r)];
                g_h2[p ^ 1][r] = fmaf(j, 1.f - h, (1.f - k) * h);
            }
        }
        const bool hasNext = (t + 1) < TSTEPS;
        if (hasNext && tid < 128) {  // early-fill: x_{t+1}
            int i = tid * 4;
            *(float4*)&svC[swz(2048 + i)] = __ldcg((const float4*)&X[(size_t)(t + 1) * 512 + i]);
        }
        gsync(target);

        // ---- phase 3: late-fill h2_new, dot W2 (out) + W1 (a_next); early-fill svA.h1_old
        {
            int i = tid * 4;
            *(float4*)&svC[swz(i)] = __ldcg((const float4*)&g_h2[p ^ 1][i]);
        }
        __syncthreads();
        if (r < 512) {
            float acc = dotrow<8>(pP3, svC, lane);
            acc = wredsum(acc);
            if (lane == 0) {
                float s = sigm(acc + b3);
                g_out[r] = s;
                Y[(size_t)t * 512 + r] = s;
            }
        } else if (r < 1024 && hasNext) {
            float acc = dotrow<10>(pP3, svC, lane);
            acc = wredsum(acc);
            if (lane == 0) g_a[r - 512] = acc + b3;
        }
        {   // early-fill: h1 state for next step's P1
            int i = tid * 4;
            *(float4*)&svA[swz(1024 + i)] = __ldcg((const float4*)&g_h1[p ^ 1][i]);
        }
        gsync(target);
    }
}

// ---------------- launch ----------------
extern "C" void kernel_launch(void* const* d_in, const int* in_sizes, int n_in,
                              void* d_out, int out_size)
{
    (void)in_sizes; (void)n_in; (void)out_size;
    const float* X   = (const float*)d_in[0];
    const float* W1  = (const float*)d_in[1];
    const float* b1  = (const float*)d_in[2];
    const float* J1W = (const float*)d_in[3];
    const float* J1b = (const float*)d_in[4];
    const float* K1W = (const float*)d_in[5];
    const float* K1b = (const float*)d_in[6];
    const float* J2W = (const float*)d_in[7];
    const float* J2b = (const float*)d_in[8];
    const float* K2W = (const float*)d_in[9];
    const float* K2b = (const float*)d_in[10];
    const float* W2  = (const float*)d_in[11];
    const float* b2  = (const float*)d_in[12];
    float* Y = (float*)d_out;

    cudaFuncSetAttribute(rnn_kernel, cudaFuncAttributeMaxDynamicSharedMemorySize, CACHE_BYTES);

    transpose_all<<<30976, dim3(32, 8)>>>(W1, J1W, K1W, J2W, K2W, W2);
    init_state<<<2, 1024>>>();
    rnn_kernel<<<NCTA, NTHREAD, CACHE_BYTES>>>(X, b1, J1b, K1b, J2b, K2b, b2, Y);
}